// round 15
// baseline (speedup 1.0000x reference)
#include <cuda_runtime.h>
#include <cuda_fp16.h>
#include <math.h>
#include <stdint.h>

#define D_MODEL 1024
#define NHEADS  16
#define DK      64
#define SEQ     2048
#define BATCH   2
#define ROWS    (BATCH*SEQ)   // 4096
#define WELEM   (D_MODEL*D_MODEL)

// fp16 scratch (allocation-free rule: __device__ globals; 16B-aligned)
__device__ __align__(16) __half g_Qh[ROWS*D_MODEL];
__device__ __align__(16) __half g_wh[4*WELEM];        // Wq,Wk,Wv,Wo hi
__device__ __align__(16) __half g_qh[ROWS*D_MODEL];   // q fp16 [B,H,S,DK] (pre-scaled)
__device__ __align__(16) __half g_kh[ROWS*D_MODEL];
__device__ __align__(16) __half g_vh[ROWS*D_MODEL];
__device__ __align__(16) __half g_ch[ROWS*D_MODEL];   // ctx fp16 [B,S,D]

// ===========================================================================
// helpers
// ===========================================================================
__device__ __forceinline__ uint32_t smem_u32(const void* p) {
    uint32_t a;
    asm("{ .reg .u64 t; cvta.to.shared.u64 t, %1; cvt.u32.u64 %0, t; }"
        : "=r"(a) : "l"(p));
    return a;
}
__device__ __forceinline__ uint32_t swz128(uint32_t off) {
    return off ^ ((off >> 3) & 0x70);
}
__device__ __forceinline__ void cp16(uint32_t smem_addr, const void* gptr) {
    asm volatile("cp.async.cg.shared.global [%0], [%1], 16;"
                 :: "r"(smem_addr), "l"(gptr));
}
#define CP_COMMIT() asm volatile("cp.async.commit_group;" ::: "memory")
#define CP_WAIT1()  asm volatile("cp.async.wait_group 1;" ::: "memory")
__device__ __forceinline__ void ldsm_x4(uint32_t* r, uint32_t addr) {
    asm volatile("ldmatrix.sync.aligned.m8n8.x4.shared.b16 {%0,%1,%2,%3}, [%4];"
                 : "=r"(r[0]), "=r"(r[1]), "=r"(r[2]), "=r"(r[3]) : "r"(addr));
}
__device__ __forceinline__ void ldsm_x4_t(uint32_t* r, uint32_t addr) {
    asm volatile("ldmatrix.sync.aligned.m8n8.x4.trans.shared.b16 {%0,%1,%2,%3}, [%4];"
                 : "=r"(r[0]), "=r"(r[1]), "=r"(r[2]), "=r"(r[3]) : "r"(addr));
}
__device__ __forceinline__ void mmah(float* c, const uint32_t* a,
                                     uint32_t b0, uint32_t b1) {
    asm volatile("mma.sync.aligned.m16n8k16.row.col.f32.f16.f16.f32 "
                 "{%0,%1,%2,%3}, {%4,%5,%6,%7}, {%8,%9}, {%0,%1,%2,%3};"
                 : "+f"(c[0]), "+f"(c[1]), "+f"(c[2]), "+f"(c[3])
                 : "r"(a[0]), "r"(a[1]), "r"(a[2]), "r"(a[3]), "r"(b0), "r"(b1));
}
// 2^t via MUFU.EX2 (sub-saturated at measured tile times).
__device__ __forceinline__ float exp2m(float t) {
    float p;
    asm("ex2.approx.f32 %0, %1;" : "=f"(p) : "f"(t));
    return p;
}
__device__ __forceinline__ uint32_t pack2h(float a, float b) {
    __half2 H = __floats2half2_rn(a, b);
    return *reinterpret_cast<uint32_t*>(&H);
}

// ===========================================================================
// one-time converts, single launch. grid (256, 8):
// y=0..3 -> quarters of Q; y=4..7 -> W_Q,W_K,W_V,W_O. 4x ILP.
// ===========================================================================
__global__ void splitAll(const float* __restrict__ Q,
                         const float* __restrict__ w0, const float* __restrict__ w1,
                         const float* __restrict__ w2, const float* __restrict__ w3,
                         __half* __restrict__ Qh, __half* __restrict__ wh) {
    int y = blockIdx.y;
    const float* s;
    __half* h;
    if (y < 4) { s = Q + (size_t)y * WELEM; h = Qh + (size_t)y * WELEM; }
    else {
        s = (y == 4) ? w0 : (y == 5) ? w1 : (y == 6) ? w2 : w3;
        h = wh + (size_t)(y - 4) * WELEM;
    }
    #pragma unroll
    for (int j = 0; j < 4; j++) {
        int i = (blockIdx.x * 1024 + j * 256 + threadIdx.x) * 4;
        float4 x = *(const float4*)(s + i);
        *(__half2*)(h + i)     = __floats2half2_rn(x.x, x.y);
        *(__half2*)(h + i + 2) = __floats2half2_rn(x.z, x.w);
    }
}

// ===========================================================================
// 1-term fp16 GEMM, cp.async 3-stage, 256 threads, warp tile 32x64, 2 CTA/SM.
// C = Ah @ Bh^T + bias, then *oscale. One barrier per K-chunk.
// Stage layout: AH +0 (16K), BH +16K. 3 stages = 96K smem.
// Loader uses swz(base + i*4096) == swz(base) + i*4096 (32-row stride is
// above the swizzle bits) -> scalar addressing, fewer registers.
// mode 0: fp32 [M,N]; mode 1: fp16 [B,H,S,DK]
// ===========================================================================
#define GST 32768
#define GT_SMEM (3*GST)   // 98304

__device__ __forceinline__ void gemm1_body(
    const __half* __restrict__ Ah, const __half* __restrict__ Bh,
    const float* __restrict__ bias,
    float* __restrict__ Cf, __half* __restrict__ Oh, int mode, float oscale)
{
    extern __shared__ __align__(1024) char smem[];
    const uint32_t sbase = smem_u32(smem);
    const int tid  = threadIdx.x;
    const int wid  = tid >> 5;
    const int lane = tid & 31;
    const int wm   = wid & 3;        // 0..3 (M)
    const int wn   = wid >> 2;       // 0..1 (N)

    const int m0 = blockIdx.y * 128;
    const int n0 = blockIdx.x * 128;

    const int r0 = tid >> 3;               // 0..31
    const int c8 = tid & 7;                // 0..7
    const uint32_t so0 = swz128((uint32_t)(r0 * 128 + c8 * 16));
    const __half* Ab = Ah + (size_t)(m0 + r0) * D_MODEL + c8 * 8;
    const __half* Bb = Bh + (size_t)(n0 + r0) * D_MODEL + c8 * 8;

    float acc[2][8][4] = {};

    // prologue: chunks 0,1 -> stages 0,1
    #pragma unroll
    for (int c = 0; c < 2; c++) {
        uint32_t st = sbase + c * GST;
        #pragma unroll
        for (int i = 0; i < 4; i++) {
            cp16(st + so0 + i * 4096,         Ab + c * 64 + (size_t)i * 32 * D_MODEL);
            cp16(st + 16384 + so0 + i * 4096, Bb + c * 64 + (size_t)i * 32 * D_MODEL);
        }
        CP_COMMIT();
    }

    int s_cur = 0, s_n2 = 2;
    for (int kc = 0; kc < 16; kc++) {
        CP_WAIT1();
        __syncthreads();   // chunk kc visible to all; stage s_n2 free of readers

        if (kc + 2 < 16) {
            uint32_t st = sbase + s_n2 * GST;
            #pragma unroll
            for (int i = 0; i < 4; i++) {
                cp16(st + so0 + i * 4096,         Ab + (kc + 2) * 64 + (size_t)i * 32 * D_MODEL);
                cp16(st + 16384 + so0 + i * 4096, Bb + (kc + 2) * 64 + (size_t)i * 32 * D_MODEL);
            }
        }
        CP_COMMIT();

        const uint32_t sbs = sbase + s_cur * GST;
        #pragma unroll
        for (int ks = 0; ks < 4; ks++) {
            uint32_t ah[2][4];
            #pragma unroll
            for (int mi = 0; mi < 2; mi++) {
                int mrow = wm * 32 + mi * 16 + (lane & 15);
                uint32_t off = swz128((uint32_t)(mrow * 128 + ks * 32 + (lane >> 4) * 16));
                ldsm_x4(ah[mi], sbs + off);
            }
            #pragma unroll
            for (int nj16 = 0; nj16 < 4; nj16++) {
                uint32_t bf[4];
                int nrow = wn * 64 + nj16 * 16 + (lane & 15);
                uint32_t off = swz128((uint32_t)(nrow * 128 + ks * 32 + (lane >> 4) * 16));
                ldsm_x4(bf, sbs + 16384 + off);
                #pragma unroll
                for (int mi = 0; mi < 2; mi++) {
                    mmah(acc[mi][nj16*2+0], ah[mi], bf[0], bf[2]);
                    mmah(acc[mi][nj16*2+1], ah[mi], bf[1], bf[3]);
                }
            }
        }
        s_cur = (s_cur == 2) ? 0 : s_cur + 1;
        s_n2  = (s_n2  == 2) ? 0 : s_n2  + 1;
    }

    #pragma unroll
    for (int mi = 0; mi < 2; mi++) {
        #pragma unroll
        for (int nj = 0; nj < 8; nj++) {
            int gj = n0 + wn * 64 + nj * 8 + (lane & 3) * 2;
            float bi0 = __ldg(bias + gj), bi1 = __ldg(bias + gj + 1);
            #pragma unroll
            for (int half = 0; half < 2; half++) {
                int gi = m0 + wm * 32 + mi * 16 + (lane >> 2) + half * 8;
                float v0 = (acc[mi][nj][half*2+0] + bi0) * oscale;
                float v1 = (acc[mi][nj][half*2+1] + bi1) * oscale;
                if (mode == 0) {
                    *(float2*)&Cf[(size_t)gi * D_MODEL + gj] = make_float2(v0, v1);
                } else {
                    int b = gi >> 11, s = gi & (SEQ - 1);
                    int h = gj >> 6,  d = gj & (DK - 1);
                    size_t idx = (((size_t)(b * NHEADS + h) * SEQ) + s) * DK + d;
                    __half2 H = __floats2half2_rn(v0, v1);
                    *(__half2*)&Oh[idx] = H;
                }
            }
        }
    }
}

#define QSCALE 0.18033688011f   // 0.125 * log2(e), folded into q

// fused Q/K/V projection: grid (8, 32, 3), z selects weight/bias/output
__global__ __launch_bounds__(256, 2)
void gemm_qkv(const __half* __restrict__ Ah, const __half* __restrict__ wh,
              const float* __restrict__ bQ, const float* __restrict__ bK,
              const float* __restrict__ bV,
              __half* __restrict__ qh, __half* __restrict__ kh,
              __half* __restrict__ vh)
{
    int z = blockIdx.z;
    const __half* Bh = wh + (size_t)z * WELEM;
    if (z == 0)      gemm1_body(Ah, Bh, bQ, nullptr, qh, 1, QSCALE);
    else if (z == 1) gemm1_body(Ah, Bh, bK, nullptr, kh, 1, 1.0f);
    else             gemm1_body(Ah, Bh, bV, nullptr, vh, 1, 1.0f);
}

__global__ __launch_bounds__(256, 2)
void gemm_o(const __half* __restrict__ ch, const __half* __restrict__ woh,
            const float* __restrict__ bO, float* __restrict__ out)
{
    gemm1_body(ch, woh, bO, out, nullptr, 0, 1.0f);
}

// ===========================================================================
// Causal flash attention, fp16 tensor-core, cp.async 3-stage pipeline of
// 128-key K/V tiles (processed as two 64-key softmax halves sharing one
// load + one barrier). 8 warps, 2 CTAs/SM target (224KB smem of 228KB).
// q pre-scaled by 0.125*log2(e): softmax is exp2(s - m) directly (all MUFU).
// Row sums on the tensor pipe (l += P @ ones); warp-voted rescale skip.
// QK 1-term; PV 1-term.
// ===========================================================================
#define FQ_SZ 16384
#define FST   32768                      // K 16K (128 rows x 128B) + V 16K
#define F_SMEM (FQ_SZ + 3*FST)           // 114688
#define ONES16 0x3C003C00u               // fp16 {1.0, 1.0}

__global__ __launch_bounds__(256, 2)
void flash_tc(const __half* __restrict__ qh, const __half* __restrict__ kh,
              const __half* __restrict__ vh, __half* __restrict__ ch)
{
    extern __shared__ __align__(1024) char smem[];
    const uint32_t sb = smem_u32(smem);
    const int tid  = threadIdx.x;
    const int wid  = tid >> 5;
    const int lane = tid & 31;
    const int qt   = (gridDim.x - 1) - blockIdx.x;
    const int bh   = blockIdx.y;
    const size_t base = (size_t)bh * SEQ * DK;
    const int nkt = qt + 1;              // 128-key tiles

    // loader geometry: 4 x 16B per thread per tensor (rows i*32 + tid/8)
    const int r0 = tid >> 3;             // 0..31
    const int c8 = tid & 7;
    const uint32_t so0 = swz128((uint32_t)(r0 * 128 + c8 * 16));
    const __half* Kb = kh + base + (size_t)r0 * DK + c8 * 8;
    const __half* Vb = vh + base + (size_t)r0 * DK + c8 * 8;

    // prologue: tiles 0,1 -> stages 0,1 (empty commits keep group accounting)
    #pragma unroll
    for (int c = 0; c < 2; c++) {
        if (c < nkt) {
            uint32_t st = sb + FQ_SZ + c * FST;
            #pragma unroll
            for (int i = 0; i < 4; i++) {
                cp16(st + so0 + i * 4096,         Kb + (size_t)(c * 128 + i * 32) * DK);
                cp16(st + 16384 + so0 + i * 4096, Vb + (size_t)(c * 128 + i * 32) * DK);
            }
        }
        CP_COMMIT();
    }

    // load Q tile -> smem (swizzled)
    #pragma unroll
    for (int i = 0; i < 4; i++) {
        int c = i * 256 + tid;
        int r = c >> 3, cc = c & 7;
        uint4 d = *(const uint4*)(qh + base + (size_t)(qt * 128 + r) * DK + cc * 8);
        asm volatile("st.shared.v4.b32 [%0], {%1,%2,%3,%4};" ::
            "r"(sb + swz128((uint32_t)(r * 128 + cc * 16))),
            "r"(d.x), "r"(d.y), "r"(d.z), "r"(d.w));
    }
    __syncthreads();

    uint32_t qf[4][4];
    #pragma unroll
    for (int ks = 0; ks < 4; ks++) {
        uint32_t off = swz128((uint32_t)((16 * wid + (lane & 15)) * 128 + ks * 32 + (lane >> 4) * 16));
        ldsm_x4(qf[ks], sb + off);
    }

    float oacc[8][4] = {};
    float lacc[4] = {};
    float m0 = -INFINITY, m1 = -INFINITY;
    const int r0g = qt * 128 + 16 * wid + (lane >> 2);

    int s_cur = 0, s_n2 = 2;
    for (int kt = 0; kt < nkt; kt++) {
        CP_WAIT1();
        __syncthreads();   // tile kt visible; stage s_n2 free of readers

        if (kt + 2 < nkt) {
            uint32_t st = sb + FQ_SZ + s_n2 * FST;
            #pragma unroll
            for (int i = 0; i < 4; i++) {
                cp16(st + so0 + i * 4096,         Kb + (size_t)((kt + 2) * 128 + i * 32) * DK);
                cp16(st + 16384 + so0 + i * 4096, Vb + (size_t)((kt + 2) * 128 + i * 32) * DK);
            }
        }
        CP_COMMIT();

        const uint32_t fsk  = sb + FQ_SZ + s_cur * FST;
        const uint32_t fsvh = fsk + 16384;

        #pragma unroll
        for (int h = 0; h < 2; h++) {
            // S = Q @ K^T on keys [kt*128 + 64h, +64)
            float sacc[8][4] = {};
            #pragma unroll
            for (int g = 0; g < 4; g++) {
                #pragma unroll
                for (int ks = 0; ks < 4; ks++) {
                    uint32_t bf[4];
                    int krow = 64 * h + 16 * g + (lane & 15);
                    uint32_t off = swz128((uint32_t)(krow * 128 + ks * 32 + (lane >> 4) * 16));
                    ldsm_x4(bf, fsk + off);
                    mmah(sacc[2*g+0], qf[ks], bf[0], bf[2]);
                    mmah(sacc[2*g+1], qf[ks], bf[1], bf[3]);
                }
            }

            if (kt * 128 + 64 * h + 63 > qt * 128 + 16 * wid) {
                #pragma unroll
                for (int t = 0; t < 8; t++) {
                    int col = kt * 128 + 64 * h + 8 * t + 2 * (lane & 3);
                    if (col     > r0g)     sacc[t][0] = -1e9f;
                    if (col + 1 > r0g)     sacc[t][1] = -1e9f;
                    if (col     > r0g + 8) sacc[t][2] = -1e9f;
                    if (col + 1 > r0g + 8) sacc[t][3] = -1e9f;
                }
            }

            float mh0 = -INFINITY, mh1 = -INFINITY;
            #pragma unroll
            for (int t = 0; t < 8; t++) {
                mh0 = fmaxf(mh0, fmaxf(sacc[t][0], sacc[t][1]));
                mh1 = fmaxf(mh1, fmaxf(sacc[t][2], sacc[t][3]));
            }
            mh0 = fmaxf(mh0, __shfl_xor_sync(0xffffffffu, mh0, 1));
            mh0 = fmaxf(mh0, __shfl_xor_sync(0xffffffffu, mh0, 2));
            mh1 = fmaxf(mh1, __shfl_xor_sync(0xffffffffu, mh1, 1));
            mh1 = fmaxf(mh1, __shfl_xor_sync(0xffffffffu, mh1, 2));
            float mn0 = fmaxf(m0, mh0), mn1 = fmaxf(m1, mh1);

            if (__any_sync(0xffffffffu, (mh0 > m0) || (mh1 > m1))) {
                float c0 = exp2m(m0 - mn0);   // ex2(-inf)=0 handles first tile
                float c1 = exp2m(m1 - mn1);
                #pragma unroll
                for (int t = 0; t < 8; t++) {
                    oacc[t][0] *= c0; oacc[t][1] *= c0;
                    oacc[t][2] *= c1; oacc[t][3] *= c1;
                }
                lacc[0] *= c0; lacc[1] *= c0;
                lacc[2] *= c1; lacc[3] *= c1;
            }
            m0 = mn0; m1 = mn1;

            #pragma unroll
            for (int t = 0; t < 8; t++) {
                sacc[t][0] = exp2m(sacc[t][0] - mn0);
                sacc[t][1] = exp2m(sacc[t][1] - mn0);
                sacc[t][2] = exp2m(sacc[t][2] - mn1);
                sacc[t][3] = exp2m(sacc[t][3] - mn1);
            }

            // O += P @ V  and  l += P @ ones (tensor pipe)
            #pragma unroll
            for (int kk = 0; kk < 4; kk++) {
                uint32_t PH[4];
                PH[0] = pack2h(sacc[2*kk  ][0], sacc[2*kk  ][1]);
                PH[1] = pack2h(sacc[2*kk  ][2], sacc[2*kk  ][3]);
                PH[2] = pack2h(sacc[2*kk+1][0], sacc[2*kk+1][1]);
                PH[3] = pack2h(sacc[2*kk+1][2], sacc[2*kk+1][3]);
                mmah(lacc, PH, ONES16, ONES16);
                int keyrow = 64 * h + kk * 16 + (lane & 7) + 8 * ((lane >> 3) & 1);
                #pragma unroll
                for (int g2 = 0; g2 < 4; g2++) {
                    uint32_t bvh[4];
                    int dkc = 16 * g2 + 8 * (lane >> 4);
                    uint32_t off = swz128((uint32_t)(keyrow * 128 + dkc * 2));
                    ldsm_x4_t(bvh, fsvh + off);
                    mmah(oacc[2*g2+0], PH, bvh[0], bvh[1]);
                    mmah(oacc[2*g2+1], PH, bvh[2], bvh[3]);
                }
            }
        }
        s_cur = (s_cur == 2) ? 0 : s_cur + 1;
        s_n2  = (s_n2  == 2) ? 0 : s_n2  + 1;
    }

    float inv0 = 1.f / lacc[0], inv1 = 1.f / lacc[2];

    int b = bh >> 4, hh = bh & 15;
    int s0 = qt * 128 + 16 * wid + (lane >> 2);
    int s1 = s0 + 8;
    #pragma unroll
    for (int t = 0; t < 8; t++) {
        int n = 8 * t + 2 * (lane & 3);
        __half2 H0 = __floats2half2_rn(oacc[t][0] * inv0, oacc[t][1] * inv0);
        __half2 H1 = __floats2half2_rn(oacc[t][2] * inv1, oacc[t][3] * inv1);
        *(__half2*)&ch[((size_t)b * SEQ + s0) * D_MODEL + hh * DK + n] = H0;
        *(__half2*)&ch[((size_t)b * SEQ + s1) * D_MODEL + hh * DK + n] = H1;
    }
}

// ---------------------------------------------------------------------------
extern "C" void kernel_launch(void* const* d_in, const int* in_sizes, int n_in,
                              void* d_out, int out_size)
{
    const float* Q   = (const float*)d_in[0];
    const float* W_Q = (const float*)d_in[1];
    const float* b_Q = (const float*)d_in[2];
    const float* W_K = (const float*)d_in[3];
    const float* b_K = (const float*)d_in[4];
    const float* W_V = (const float*)d_in[5];
    const float* b_V = (const float*)d_in[6];
    const float* W_O = (const float*)d_in[7];
    const float* b_O = (const float*)d_in[8];
    float* out = (float*)d_out;

    __half *Qh, *wh, *qh, *kh, *vh, *ch;
    cudaGetSymbolAddress((void**)&Qh, g_Qh);
    cudaGetSymbolAddress((void**)&wh, g_wh);
    cudaGetSymbolAddress((void**)&qh, g_qh);
    cudaGetSymbolAddress((void**)&kh, g_kh);
    cudaGetSymbolAddress((void**)&vh, g_vh);
    cudaGetSymbolAddress((void**)&ch, g_ch);

    cudaFuncSetAttribute(gemm_qkv, cudaFuncAttributeMaxDynamicSharedMemorySize, GT_SMEM);
    cudaFuncSetAttribute(gemm_o,   cudaFuncAttributeMaxDynamicSharedMemorySize, GT_SMEM);
    cudaFuncSetAttribute(flash_tc, cudaFuncAttributeMaxDynamicSharedMemorySize, F_SMEM);

    splitAll<<<dim3(WELEM / 16 / 256, 8), 256>>>(Q, W_Q, W_K, W_V, W_O, Qh, wh);

    gemm_qkv<<<dim3(8, 32, 3), 256, GT_SMEM>>>(Qh, wh, b_Q, b_K, b_V, qh, kh, vh);

    flash_tc<<<dim3(SEQ / 128, BATCH * NHEADS), 256, F_SMEM>>>(qh, kh, vh, ch);

    gemm_o<<<dim3(8, 32), 256, GT_SMEM>>>(ch, wh + 3 * (size_t)WELEM, b_O, out);
}

// round 16
// speedup vs baseline: 1.0193x; 1.0193x over previous
#include <cuda_runtime.h>
#include <cuda_fp16.h>
#include <math.h>
#include <stdint.h>

#define D_MODEL 1024
#define NHEADS  16
#define DK      64
#define SEQ     2048
#define BATCH   2
#define ROWS    (BATCH*SEQ)   // 4096
#define WELEM   (D_MODEL*D_MODEL)

// fp16 scratch (allocation-free rule: __device__ globals; 16B-aligned)
__device__ __align__(16) __half g_Qh[ROWS*D_MODEL];
__device__ __align__(16) __half g_wh[4*WELEM];        // Wq,Wk,Wv,Wo hi
__device__ __align__(16) __half g_qh[ROWS*D_MODEL];   // q fp16 [B,H,S,DK] (pre-scaled)
__device__ __align__(16) __half g_kh[ROWS*D_MODEL];
__device__ __align__(16) __half g_vh[ROWS*D_MODEL];
__device__ __align__(16) __half g_ch[ROWS*D_MODEL];   // ctx fp16 [B,S,D]

// ===========================================================================
// helpers
// ===========================================================================
__device__ __forceinline__ uint32_t smem_u32(const void* p) {
    uint32_t a;
    asm("{ .reg .u64 t; cvta.to.shared.u64 t, %1; cvt.u32.u64 %0, t; }"
        : "=r"(a) : "l"(p));
    return a;
}
__device__ __forceinline__ uint32_t swz128(uint32_t off) {
    return off ^ ((off >> 3) & 0x70);
}
__device__ __forceinline__ void cp16(uint32_t smem_addr, const void* gptr) {
    asm volatile("cp.async.cg.shared.global [%0], [%1], 16;"
                 :: "r"(smem_addr), "l"(gptr));
}
#define CP_COMMIT() asm volatile("cp.async.commit_group;" ::: "memory")
#define CP_WAIT1()  asm volatile("cp.async.wait_group 1;" ::: "memory")
#define CP_WAIT2()  asm volatile("cp.async.wait_group 2;" ::: "memory")
__device__ __forceinline__ void ldsm_x4(uint32_t* r, uint32_t addr) {
    asm volatile("ldmatrix.sync.aligned.m8n8.x4.shared.b16 {%0,%1,%2,%3}, [%4];"
                 : "=r"(r[0]), "=r"(r[1]), "=r"(r[2]), "=r"(r[3]) : "r"(addr));
}
__device__ __forceinline__ void ldsm_x4_t(uint32_t* r, uint32_t addr) {
    asm volatile("ldmatrix.sync.aligned.m8n8.x4.trans.shared.b16 {%0,%1,%2,%3}, [%4];"
                 : "=r"(r[0]), "=r"(r[1]), "=r"(r[2]), "=r"(r[3]) : "r"(addr));
}
__device__ __forceinline__ void mmah(float* c, const uint32_t* a,
                                     uint32_t b0, uint32_t b1) {
    asm volatile("mma.sync.aligned.m16n8k16.row.col.f32.f16.f16.f32 "
                 "{%0,%1,%2,%3}, {%4,%5,%6,%7}, {%8,%9}, {%0,%1,%2,%3};"
                 : "+f"(c[0]), "+f"(c[1]), "+f"(c[2]), "+f"(c[3])
                 : "r"(a[0]), "r"(a[1]), "r"(a[2]), "r"(a[3]), "r"(b0), "r"(b1));
}
// 2^t via MUFU.EX2 (sub-saturated at measured tile times).
__device__ __forceinline__ float exp2m(float t) {
    float p;
    asm("ex2.approx.f32 %0, %1;" : "=f"(p) : "f"(t));
    return p;
}
__device__ __forceinline__ uint32_t pack2h(float a, float b) {
    __half2 H = __floats2half2_rn(a, b);
    return *reinterpret_cast<uint32_t*>(&H);
}

// ===========================================================================
// one-time converts, single launch. grid (256, 8):
// y=0..3 -> quarters of Q; y=4..7 -> W_Q,W_K,W_V,W_O. 4x ILP.
// ===========================================================================
__global__ void splitAll(const float* __restrict__ Q,
                         const float* __restrict__ w0, const float* __restrict__ w1,
                         const float* __restrict__ w2, const float* __restrict__ w3,
                         __half* __restrict__ Qh, __half* __restrict__ wh) {
    int y = blockIdx.y;
    const float* s;
    __half* h;
    if (y < 4) { s = Q + (size_t)y * WELEM; h = Qh + (size_t)y * WELEM; }
    else {
        s = (y == 4) ? w0 : (y == 5) ? w1 : (y == 6) ? w2 : w3;
        h = wh + (size_t)(y - 4) * WELEM;
    }
    #pragma unroll
    for (int j = 0; j < 4; j++) {
        int i = (blockIdx.x * 1024 + j * 256 + threadIdx.x) * 4;
        float4 x = *(const float4*)(s + i);
        *(__half2*)(h + i)     = __floats2half2_rn(x.x, x.y);
        *(__half2*)(h + i + 2) = __floats2half2_rn(x.z, x.w);
    }
}

// ===========================================================================
// 1-term fp16 GEMM, cp.async 3-stage, 256 threads, warp tile 32x64, 2 CTA/SM.
// C = Ah @ Bh^T + bias, then *oscale. One barrier per K-chunk.
// Stage layout: AH +0 (16K), BH +16K. 3 stages = 96K smem.  (R14 body)
// mode 0: fp32 [M,N]; mode 1: fp16 [B,H,S,DK]
// ===========================================================================
#define GST 32768
#define GT_SMEM (3*GST)   // 98304

__device__ __forceinline__ void gemm1_body(
    const __half* __restrict__ Ah, const __half* __restrict__ Bh,
    const float* __restrict__ bias,
    float* __restrict__ Cf, __half* __restrict__ Oh, int mode, float oscale)
{
    extern __shared__ __align__(1024) char smem[];
    const uint32_t sbase = smem_u32(smem);
    const int tid  = threadIdx.x;
    const int wid  = tid >> 5;
    const int lane = tid & 31;
    const int wm   = wid & 3;        // 0..3 (M)
    const int wn   = wid >> 2;       // 0..1 (N)

    const int m0 = blockIdx.y * 128;
    const int n0 = blockIdx.x * 128;

    int rowi[4], c8i[4];
    uint32_t soff[4];
    #pragma unroll
    for (int i = 0; i < 4; i++) {
        int g = i * 256 + tid;       // 0..1023
        rowi[i] = g >> 3;            // 0..127
        c8i[i]  = g & 7;
        soff[i] = swz128((uint32_t)(rowi[i] * 128 + c8i[i] * 16));
    }

    float acc[2][8][4] = {};

    // prologue: chunks 0,1 -> stages 0,1
    #pragma unroll
    for (int c = 0; c < 2; c++) {
        uint32_t st = sbase + c * GST;
        #pragma unroll
        for (int i = 0; i < 4; i++) {
            size_t ao = (size_t)(m0 + rowi[i]) * D_MODEL + c * 64 + c8i[i] * 8;
            size_t bo = (size_t)(n0 + rowi[i]) * D_MODEL + c * 64 + c8i[i] * 8;
            cp16(st + soff[i],         Ah + ao);
            cp16(st + 16384 + soff[i], Bh + bo);
        }
        CP_COMMIT();
    }

    int s_cur = 0, s_n2 = 2;
    for (int kc = 0; kc < 16; kc++) {
        CP_WAIT1();
        __syncthreads();   // chunk kc visible to all; stage s_n2 free of readers

        if (kc + 2 < 16) {
            uint32_t st = sbase + s_n2 * GST;
            #pragma unroll
            for (int i = 0; i < 4; i++) {
                size_t ao = (size_t)(m0 + rowi[i]) * D_MODEL + (kc + 2) * 64 + c8i[i] * 8;
                size_t bo = (size_t)(n0 + rowi[i]) * D_MODEL + (kc + 2) * 64 + c8i[i] * 8;
                cp16(st + soff[i],         Ah + ao);
                cp16(st + 16384 + soff[i], Bh + bo);
            }
        }
        CP_COMMIT();

        const uint32_t sbs = sbase + s_cur * GST;
        #pragma unroll
        for (int ks = 0; ks < 4; ks++) {
            uint32_t ah[2][4];
            #pragma unroll
            for (int mi = 0; mi < 2; mi++) {
                int mrow = wm * 32 + mi * 16 + (lane & 15);
                uint32_t off = swz128((uint32_t)(mrow * 128 + ks * 32 + (lane >> 4) * 16));
                ldsm_x4(ah[mi], sbs + off);
            }
            #pragma unroll
            for (int nj16 = 0; nj16 < 4; nj16++) {
                uint32_t bf[4];
                int nrow = wn * 64 + nj16 * 16 + (lane & 15);
                uint32_t off = swz128((uint32_t)(nrow * 128 + ks * 32 + (lane >> 4) * 16));
                ldsm_x4(bf, sbs + 16384 + off);
                #pragma unroll
                for (int mi = 0; mi < 2; mi++) {
                    mmah(acc[mi][nj16*2+0], ah[mi], bf[0], bf[2]);
                    mmah(acc[mi][nj16*2+1], ah[mi], bf[1], bf[3]);
                }
            }
        }
        s_cur = (s_cur == 2) ? 0 : s_cur + 1;
        s_n2  = (s_n2  == 2) ? 0 : s_n2  + 1;
    }

    #pragma unroll
    for (int mi = 0; mi < 2; mi++) {
        #pragma unroll
        for (int nj = 0; nj < 8; nj++) {
            int gj = n0 + wn * 64 + nj * 8 + (lane & 3) * 2;
            float bi0 = __ldg(bias + gj), bi1 = __ldg(bias + gj + 1);
            #pragma unroll
            for (int half = 0; half < 2; half++) {
                int gi = m0 + wm * 32 + mi * 16 + (lane >> 2) + half * 8;
                float v0 = (acc[mi][nj][half*2+0] + bi0) * oscale;
                float v1 = (acc[mi][nj][half*2+1] + bi1) * oscale;
                if (mode == 0) {
                    *(float2*)&Cf[(size_t)gi * D_MODEL + gj] = make_float2(v0, v1);
                } else {
                    int b = gi >> 11, s = gi & (SEQ - 1);
                    int h = gj >> 6,  d = gj & (DK - 1);
                    size_t idx = (((size_t)(b * NHEADS + h) * SEQ) + s) * DK + d;
                    __half2 H = __floats2half2_rn(v0, v1);
                    *(__half2*)&Oh[idx] = H;
                }
            }
        }
    }
}

#define QSCALE 0.18033688011f   // 0.125 * log2(e), folded into q

// fused Q/K/V projection: grid (8, 32, 3), z selects weight/bias/output
__global__ __launch_bounds__(256, 2)
void gemm_qkv(const __half* __restrict__ Ah, const __half* __restrict__ wh,
              const float* __restrict__ bQ, const float* __restrict__ bK,
              const float* __restrict__ bV,
              __half* __restrict__ qh, __half* __restrict__ kh,
              __half* __restrict__ vh)
{
    int z = blockIdx.z;
    const __half* Bh = wh + (size_t)z * WELEM;
    if (z == 0)      gemm1_body(Ah, Bh, bQ, nullptr, qh, 1, QSCALE);
    else if (z == 1) gemm1_body(Ah, Bh, bK, nullptr, kh, 1, 1.0f);
    else             gemm1_body(Ah, Bh, bV, nullptr, vh, 1, 1.0f);
}

__global__ __launch_bounds__(256, 2)
void gemm_o(const __half* __restrict__ ch, const __half* __restrict__ woh,
            const float* __restrict__ bO, float* __restrict__ out)
{
    gemm1_body(ch, woh, bO, out, nullptr, 0, 1.0f);
}

// ===========================================================================
// Causal flash attention, fp16 tensor-core, cp.async 4-stage K/V pipeline
// (64-key tiles, prefetch distance 3). 8 warps, 2 CTAs/SM (80KB smem/CTA).
// q pre-scaled by 0.125*log2(e): softmax is exp2(s - m) directly (all MUFU).
// Row sums on the tensor pipe (l += P @ ones); warp-voted rescale skip.
// QK 1-term; PV 1-term.
// ===========================================================================
#define FQ_SZ 16384
#define FST   16384
#define F_SMEM (FQ_SZ + 4*FST)   // 81920
#define ONES16 0x3C003C00u       // fp16 {1.0, 1.0}

__global__ __launch_bounds__(256, 2)
void flash_tc(const __half* __restrict__ qh, const __half* __restrict__ kh,
              const __half* __restrict__ vh, __half* __restrict__ ch)
{
    extern __shared__ __align__(1024) char smem[];
    const uint32_t sb = smem_u32(smem);
    const int tid  = threadIdx.x;
    const int wid  = tid >> 5;
    const int lane = tid & 31;
    const int qt   = (gridDim.x - 1) - blockIdx.x;
    const int bh   = blockIdx.y;
    const size_t base = (size_t)bh * SEQ * DK;
    const int nkt = 2 * qt + 2;    // 64-key tiles, >= 2 always

    // loader geometry (shared by K and V)
    int lr[2], lc8[2];
    uint32_t lso[2];
    #pragma unroll
    for (int i = 0; i < 2; i++) {
        int c = i * 256 + tid;          // 0..511
        lr[i]  = c >> 3;
        lc8[i] = c & 7;
        lso[i] = swz128((uint32_t)(lr[i] * 128 + lc8[i] * 16));
    }

    // prologue: tiles 0..2 -> stages 0..2 (commits unconditional for accounting)
    #pragma unroll
    for (int c = 0; c < 3; c++) {
        if (c < nkt) {
            uint32_t st = sb + FQ_SZ + c * FST;
            #pragma unroll
            for (int i = 0; i < 2; i++) {
                size_t go = base + (size_t)(c * 64 + lr[i]) * DK + lc8[i] * 8;
                cp16(st + lso[i],        kh + go);
                cp16(st + 8192 + lso[i], vh + go);
            }
        }
        CP_COMMIT();
    }

    // load Q tile -> smem (swizzled)
    #pragma unroll
    for (int i = 0; i < 4; i++) {
        int c = i * 256 + tid;
        int r = c >> 3, c8 = c & 7;
        uint4 d = *(const uint4*)(qh + base + (size_t)(qt * 128 + r) * DK + c8 * 8);
        asm volatile("st.shared.v4.b32 [%0], {%1,%2,%3,%4};" ::
            "r"(sb + swz128((uint32_t)(r * 128 + c8 * 16))),
            "r"(d.x), "r"(d.y), "r"(d.z), "r"(d.w));
    }
    __syncthreads();

    uint32_t qf[4][4];
    #pragma unroll
    for (int ks = 0; ks < 4; ks++) {
        uint32_t off = swz128((uint32_t)((16 * wid + (lane & 15)) * 128 + ks * 32 + (lane >> 4) * 16));
        ldsm_x4(qf[ks], sb + off);
    }

    float oacc[8][4] = {};
    float lacc[4] = {};            // tensor-pipe row sums
    float m0 = -INFINITY, m1 = -INFINITY;
    const int r0g = qt * 128 + 16 * wid + (lane >> 2);

    for (int kt = 0; kt < nkt; kt++) {
        CP_WAIT2();
        __syncthreads();   // tile kt visible; stage (kt+3)&3's readers done

        if (kt + 3 < nkt) {
            uint32_t st = sb + FQ_SZ + ((kt + 3) & 3) * FST;
            #pragma unroll
            for (int i = 0; i < 2; i++) {
                size_t go = base + (size_t)((kt + 3) * 64 + lr[i]) * DK + lc8[i] * 8;
                cp16(st + lso[i],        kh + go);
                cp16(st + 8192 + lso[i], vh + go);
            }
        }
        CP_COMMIT();

        const uint32_t fsk  = sb + FQ_SZ + (kt & 3) * FST;
        const uint32_t fsvh = fsk + 8192;

        // S = Q @ K^T (scores already in log2 domain via q pre-scale)
        float sacc[8][4] = {};
        #pragma unroll
        for (int g = 0; g < 4; g++) {
            #pragma unroll
            for (int ks = 0; ks < 4; ks++) {
                uint32_t bf[4];
                uint32_t off = swz128((uint32_t)((16 * g + (lane & 15)) * 128 + ks * 32 + (lane >> 4) * 16));
                ldsm_x4(bf, fsk + off);
                mmah(sacc[2*g+0], qf[ks], bf[0], bf[2]);
                mmah(sacc[2*g+1], qf[ks], bf[1], bf[3]);
            }
        }

        if (kt * 64 + 63 > qt * 128 + 16 * wid) {
            #pragma unroll
            for (int t = 0; t < 8; t++) {
                int col = kt * 64 + 8 * t + 2 * (lane & 3);
                if (col     > r0g)     sacc[t][0] = -1e9f;
                if (col + 1 > r0g)     sacc[t][1] = -1e9f;
                if (col     > r0g + 8) sacc[t][2] = -1e9f;
                if (col + 1 > r0g + 8) sacc[t][3] = -1e9f;
            }
        }

        float mh0 = -INFINITY, mh1 = -INFINITY;
        #pragma unroll
        for (int t = 0; t < 8; t++) {
            mh0 = fmaxf(mh0, fmaxf(sacc[t][0], sacc[t][1]));
            mh1 = fmaxf(mh1, fmaxf(sacc[t][2], sacc[t][3]));
        }
        mh0 = fmaxf(mh0, __shfl_xor_sync(0xffffffffu, mh0, 1));
        mh0 = fmaxf(mh0, __shfl_xor_sync(0xffffffffu, mh0, 2));
        mh1 = fmaxf(mh1, __shfl_xor_sync(0xffffffffu, mh1, 1));
        mh1 = fmaxf(mh1, __shfl_xor_sync(0xffffffffu, mh1, 2));
        float mn0 = fmaxf(m0, mh0), mn1 = fmaxf(m1, mh1);

        // rescale only when some row's max actually grew (warp vote)
        if (__any_sync(0xffffffffu, (mh0 > m0) || (mh1 > m1))) {
            float c0 = exp2m(m0 - mn0);   // ex2(-inf)=0 handles first tile
            float c1 = exp2m(m1 - mn1);
            #pragma unroll
            for (int t = 0; t < 8; t++) {
                oacc[t][0] *= c0; oacc[t][1] *= c0;
                oacc[t][2] *= c1; oacc[t][3] *= c1;
            }
            lacc[0] *= c0; lacc[1] *= c0;
            lacc[2] *= c1; lacc[3] *= c1;
        }
        m0 = mn0; m1 = mn1;

        // p = 2^(s - m), all on MUFU
        #pragma unroll
        for (int t = 0; t < 8; t++) {
            sacc[t][0] = exp2m(sacc[t][0] - mn0);
            sacc[t][1] = exp2m(sacc[t][1] - mn0);
            sacc[t][2] = exp2m(sacc[t][2] - mn1);
            sacc[t][3] = exp2m(sacc[t][3] - mn1);
        }

        // O += P @ V  and  l += P @ ones   (both on tensor pipe)
        #pragma unroll
        for (int kk = 0; kk < 4; kk++) {
            uint32_t PH[4];
            PH[0] = pack2h(sacc[2*kk  ][0], sacc[2*kk  ][1]);
            PH[1] = pack2h(sacc[2*kk  ][2], sacc[2*kk  ][3]);
            PH[2] = pack2h(sacc[2*kk+1][0], sacc[2*kk+1][1]);
            PH[3] = pack2h(sacc[2*kk+1][2], sacc[2*kk+1][3]);
            mmah(lacc, PH, ONES16, ONES16);
            int keyrow = kk * 16 + (lane & 7) + 8 * ((lane >> 3) & 1);
            #pragma unroll
            for (int g2 = 0; g2 < 4; g2++) {
                uint32_t bvh[4];
                int dkc = 16 * g2 + 8 * (lane >> 4);
                uint32_t off = swz128((uint32_t)(keyrow * 128 + dkc * 2));
                ldsm_x4_t(bvh, fsvh + off);
                mmah(oacc[2*g2+0], PH, bvh[0], bvh[1]);
                mmah(oacc[2*g2+1], PH, bvh[2], bvh[3]);
            }
        }
    }

    // lacc[0]/lacc[2] hold complete row sums (mma reduced across the quad)
    float inv0 = 1.f / lacc[0], inv1 = 1.f / lacc[2];

    int b = bh >> 4, hh = bh & 15;
    int s0 = qt * 128 + 16 * wid + (lane >> 2);
    int s1 = s0 + 8;
    #pragma unroll
    for (int t = 0; t < 8; t++) {
        int n = 8 * t + 2 * (lane & 3);
        __half2 H0 = __floats2half2_rn(oacc[t][0] * inv0, oacc[t][1] * inv0);
        __half2 H1 = __floats2half2_rn(oacc[t][2] * inv1, oacc[t][3] * inv1);
        *(__half2*)&ch[((size_t)b * SEQ + s0) * D_MODEL + hh * DK + n] = H0;
        *(__half2*)&ch[((size_t)b * SEQ + s1) * D_MODEL + hh * DK + n] = H1;
    }
}

// ---------------------------------------------------------------------------
extern "C" void kernel_launch(void* const* d_in, const int* in_sizes, int n_in,
                              void* d_out, int out_size)
{
    const float* Q   = (const float*)d_in[0];
    const float* W_Q = (const float*)d_in[1];
    const float* b_Q = (const float*)d_in[2];
    const float* W_K = (const float*)d_in[3];
    const float* b_K = (const float*)d_in[4];
    const float* W_V = (const float*)d_in[5];
    const float* b_V = (const float*)d_in[6];
    const float* W_O = (const float*)d_in[7];
    const float* b_O = (const float*)d_in[8];
    float* out = (float*)d_out;

    __half *Qh, *wh, *qh, *kh, *vh, *ch;
    cudaGetSymbolAddress((void**)&Qh, g_Qh);
    cudaGetSymbolAddress((void**)&wh, g_wh);
    cudaGetSymbolAddress((void**)&qh, g_qh);
    cudaGetSymbolAddress((void**)&kh, g_kh);
    cudaGetSymbolAddress((void**)&vh, g_vh);
    cudaGetSymbolAddress((void**)&ch, g_ch);

    cudaFuncSetAttribute(gemm_qkv, cudaFuncAttributeMaxDynamicSharedMemorySize, GT_SMEM);
    cudaFuncSetAttribute(gemm_o,   cudaFuncAttributeMaxDynamicSharedMemorySize, GT_SMEM);
    cudaFuncSetAttribute(flash_tc, cudaFuncAttributeMaxDynamicSharedMemorySize, F_SMEM);

    splitAll<<<dim3(WELEM / 16 / 256, 8), 256>>>(Q, W_Q, W_K, W_V, W_O, Qh, wh);

    gemm_qkv<<<dim3(8, 32, 3), 256, GT_SMEM>>>(Qh, wh, b_Q, b_K, b_V, qh, kh, vh);

    flash_tc<<<dim3(SEQ / 128, BATCH * NHEADS), 256, F_SMEM>>>(qh, kh, vh, ch);

    gemm_o<<<dim3(8, 32), 256, GT_SMEM>>>(ch, wh + 3 * (size_t)WELEM, b_O, out);
}